// round 11
// baseline (speedup 1.0000x reference)
#include <cuda_runtime.h>
#include <cuda_bf16.h>
#include <math.h>
#include <stdint.h>

#define BB 2
#define LL 2048
#define DD 1024
#define HH 16
#define DH 64
#define TK 32
#define NCAND 48
#define SCALE 0.125f   // 1/sqrt(64)

// ---------------- scratch (device globals; no allocs allowed) ----------------
__device__ float g_q   [(size_t)BB*LL*DD];
__device__ float g_kv  [(size_t)BB*LL*2*DH];
__device__ float g_k   [(size_t)BB*LL*DH];
__device__ float g_v   [(size_t)BB*LL*DH];
__device__ float g_part[BB*16*128];
__device__ float g_norm[BB*128];
__device__ float g_sims[(size_t)BB*HH*LL*LL];       // 512 MB
__device__ float g_rowmax[BB*HH*LL];
__device__ float g_rowsum[BB*HH*LL];
__device__ int   g_cand[(size_t)BB*HH*LL*NCAND];    // coarse candidates
__device__ float g_attn[(size_t)BB*LL*DD];
// bf16 2-splits for the smooth-path MMAs
__device__ __nv_bfloat16 g_ah [(size_t)BB*LL*DD];   // attn split (wconcat A)
__device__ __nv_bfloat16 g_al [(size_t)BB*LL*DD];
__device__ __nv_bfloat16 g_bth[(size_t)DD*DD];      // w_concat^T split
__device__ __nv_bfloat16 g_btl[(size_t)DD*DD];
__device__ __nv_bfloat16 g_qh [(size_t)BB*LL*DD];   // q split for sims
__device__ __nv_bfloat16 g_ql [(size_t)BB*LL*DD];
__device__ __nv_bfloat16 g_kh [(size_t)BB*LL*DH];   // k split for sims
__device__ __nv_bfloat16 g_kl [(size_t)BB*LL*DH];
__device__ __nv_bfloat16 g_vth[(size_t)BB*DH*LL];   // v^T split for pv
__device__ __nv_bfloat16 g_vtl[(size_t)BB*DH*LL];

// ---------------- helpers ----------------
__device__ __forceinline__ uint32_t smem_u32(const void* p) {
    uint32_t a;
    asm("{ .reg .u64 t; cvta.to.shared.u64 t, %1; cvt.u32.u64 %0, t; }" : "=r"(a) : "l"(p));
    return a;
}
#define LDSM4(r0, r1, r2, r3, a) \
    asm volatile("ldmatrix.sync.aligned.m8n8.x4.shared.b16 {%0,%1,%2,%3}, [%4];" \
        : "=r"(r0), "=r"(r1), "=r"(r2), "=r"(r3) : "r"(a))
#define MMA_BF16(d, a0, a1, a2, a3, b0, b1) \
    asm volatile("mma.sync.aligned.m16n8k16.row.col.f32.bf16.bf16.f32 " \
        "{%0,%1,%2,%3}, {%4,%5,%6,%7}, {%8,%9}, {%0,%1,%2,%3};" \
        : "+f"((d)[0]), "+f"((d)[1]), "+f"((d)[2]), "+f"((d)[3]) \
        : "r"(a0), "r"(a1), "r"(a2), "r"(a3), "r"(b0), "r"(b1))

__device__ __forceinline__ uint32_t bpack(float a, float b) {
    __nv_bfloat162 t = __floats2bfloat162_rn(a, b);
    return *(uint32_t*)&t;
}
__device__ __forceinline__ unsigned f2key(float x) {
    unsigned u = __float_as_uint(x);
    return u ^ ((unsigned)((int)u >> 31) | 0x80000000u);
}
__device__ __forceinline__ float key2f(unsigned k) {
    unsigned u = (k & 0x80000000u) ? (k ^ 0x80000000u) : ~k;
    return __uint_as_float(u);
}

// ---------------- fragment load / mma helpers ----------------
__device__ __forceinline__ void ld_afrag(uint32_t sb, int base, int wm, int lrow,
                                         int chunk, uint32_t af[4][4]) {
#pragma unroll
    for (int mf = 0; mf < 4; mf++) {
        int row = wm*64 + mf*16 + lrow;
        uint32_t ad = sb + base + row*128 + ((chunk ^ (row & 7)) << 4);
        LDSM4(af[mf][0], af[mf][1], af[mf][2], af[mf][3], ad);
    }
}
__device__ __forceinline__ void ld_bfrag(uint32_t sb, int base, int wn, int lrow,
                                         int chunk, uint32_t bb[4][2]) {
#pragma unroll
    for (int p = 0; p < 2; p++) {
        int row = wn*32 + p*16 + lrow;
        uint32_t bd = sb + base + row*128 + ((chunk ^ (row & 7)) << 4);
        uint32_t t0, t1, t2, t3;
        LDSM4(t0, t1, t2, t3, bd);
        bb[p*2+0][0] = t0; bb[p*2+0][1] = t2;
        bb[p*2+1][0] = t1; bb[p*2+1][1] = t3;
    }
}
__device__ __forceinline__ void do_mma16(float acc[4][4][4], uint32_t af[4][4],
                                         uint32_t bb[4][2]) {
#pragma unroll
    for (int mf = 0; mf < 4; mf++)
#pragma unroll
        for (int nf = 0; nf < 4; nf++)
            MMA_BF16(acc[mf][nf], af[mf][0], af[mf][1], af[mf][2], af[mf][3],
                     bb[nf][0], bb[nf][1]);
}

// ---------------- fp32 SIMT GEMM (wq / kv — bitwise-faithful sequential-k) --
// C(MxN) = A(MxK) @ B(KxN). 128x128 tile, 256 threads, 8x8 micro.
__global__ __launch_bounds__(256) void sgemm_kernel(
    const float* __restrict__ A, const float* __restrict__ Bm,
    float* __restrict__ C, int Mdim, int Ndim, int Kdim)
{
    __shared__ float As[128*33];
    __shared__ float Bs[32*132];
    int tid  = threadIdx.x;
    int brow = blockIdx.y * 128;
    int bcol = blockIdx.x * 128;
    int rowg = tid >> 4;
    int c0   = (tid & 15) * 4;
    float acc[8][8];
#pragma unroll
    for (int i = 0; i < 8; i++)
#pragma unroll
        for (int j = 0; j < 8; j++) acc[i][j] = 0.f;

    for (int kt = 0; kt < Kdim; kt += 32) {
#pragma unroll
        for (int i = 0; i < 4; i++) {
            int f4 = tid + i*256;
            int r = f4 >> 3, c4 = f4 & 7;
            float4 v = *(const float4*)(A + (size_t)(brow + r)*Kdim + kt + c4*4);
            As[r*33 + c4*4+0] = v.x; As[r*33 + c4*4+1] = v.y;
            As[r*33 + c4*4+2] = v.z; As[r*33 + c4*4+3] = v.w;
        }
#pragma unroll
        for (int i = 0; i < 4; i++) {
            int f4 = tid + i*256;
            int r = f4 >> 5, c4 = f4 & 31;
            *(float4*)&Bs[r*132 + c4*4] =
                *(const float4*)(Bm + (size_t)(kt + r)*Ndim + bcol + c4*4);
        }
        __syncthreads();
#pragma unroll 8
        for (int kk = 0; kk < 32; kk++) {
            float av[8];
#pragma unroll
            for (int i = 0; i < 8; i++) av[i] = As[(rowg + 16*i)*33 + kk];
            float4 b0 = *(float4*)&Bs[kk*132 + c0];
            float4 b1 = *(float4*)&Bs[kk*132 + 64 + c0];
#pragma unroll
            for (int i = 0; i < 8; i++) {
                acc[i][0] += av[i]*b0.x; acc[i][1] += av[i]*b0.y;
                acc[i][2] += av[i]*b0.z; acc[i][3] += av[i]*b0.w;
                acc[i][4] += av[i]*b1.x; acc[i][5] += av[i]*b1.y;
                acc[i][6] += av[i]*b1.z; acc[i][7] += av[i]*b1.w;
            }
        }
        __syncthreads();
    }
#pragma unroll
    for (int i = 0; i < 8; i++) {
        size_t r = (size_t)(brow + rowg + 16*i)*Ndim + bcol;
        *(float4*)(C + r + c0)      = make_float4(acc[i][0],acc[i][1],acc[i][2],acc[i][3]);
        *(float4*)(C + r + 64 + c0) = make_float4(acc[i][4],acc[i][5],acc[i][6],acc[i][7]);
    }
}

// ---------------- bf16x3 GEMM body (sims coarse / wconcat — smooth) ---------
__device__ __forceinline__ void mma_gemm_body3(
    const __nv_bfloat16* __restrict__ Ah, const __nv_bfloat16* __restrict__ Al, int lda,
    const __nv_bfloat16* __restrict__ Bh, const __nv_bfloat16* __restrict__ Bl, int ldb,
    float* __restrict__ C, int ldc, int Kdim, char* smem)
{
    uint32_t sb = smem_u32(smem);
    int tid = threadIdx.x, lane = tid & 31, wid = tid >> 5;
    int wm = wid >> 2, wn = wid & 3;
    int lrow = lane & 15, lhalf = lane >> 4;
    float acc[4][4][4];
#pragma unroll
    for (int i = 0; i < 4; i++)
#pragma unroll
        for (int j = 0; j < 4; j++)
#pragma unroll
            for (int q = 0; q < 4; q++) acc[i][j][q] = 0.f;

    int r0 = tid >> 3, cc = tid & 7;
    for (int kt = 0; kt < Kdim; kt += 64) {
#pragma unroll
        for (int t = 0; t < 16; t++) {
            int tile = t >> 2;
            int r = r0 + (t & 3)*32;
            int ld = (tile < 2) ? lda : ldb;
            const __nv_bfloat16* sp =
                ((tile == 0) ? Ah : (tile == 1) ? Al : (tile == 2) ? Bh : Bl)
                + (size_t)r*ld + kt + cc*8;
            *(uint4*)(smem + tile*16384 + r*128 + ((cc ^ (r & 7)) << 4)) = *(const uint4*)sp;
        }
        __syncthreads();
#pragma unroll
        for (int s = 0; s < 4; s++) {
            int chunk = s*2 + lhalf;
            uint32_t af[4][4], bb[4][2];
            ld_bfrag(sb, 32768, wn, lrow, chunk, bb);       // B hi
            ld_afrag(sb, 0,     wm, lrow, chunk, af); do_mma16(acc, af, bb);
            ld_afrag(sb, 16384, wm, lrow, chunk, af); do_mma16(acc, af, bb);
            ld_bfrag(sb, 49152, wn, lrow, chunk, bb);       // B lo
            ld_afrag(sb, 0,     wm, lrow, chunk, af); do_mma16(acc, af, bb);
        }
        __syncthreads();
    }
#pragma unroll
    for (int mf = 0; mf < 4; mf++) {
        int r = wm*64 + mf*16 + (lane >> 2);
#pragma unroll
        for (int nf = 0; nf < 4; nf++) {
            int c = wn*32 + nf*8 + (lane & 3)*2;
            *(float2*)(C + (size_t)r*ldc + c)       = make_float2(acc[mf][nf][0], acc[mf][nf][1]);
            *(float2*)(C + (size_t)(r + 8)*ldc + c) = make_float2(acc[mf][nf][2], acc[mf][nf][3]);
        }
    }
}

__global__ __launch_bounds__(256) void mma_gemm3_kernel(
    const __nv_bfloat16* __restrict__ Ah, const __nv_bfloat16* __restrict__ Al,
    const __nv_bfloat16* __restrict__ Bth, const __nv_bfloat16* __restrict__ Btl,
    float* __restrict__ C, int Ndim, int Kdim)
{
    extern __shared__ char smem[];
    int brow = blockIdx.y * 128, bcol = blockIdx.x * 128;
    mma_gemm_body3(Ah + (size_t)brow*Kdim, Al + (size_t)brow*Kdim, Kdim,
                   Bth + (size_t)bcol*Kdim, Btl + (size_t)bcol*Kdim, Kdim,
                   C + (size_t)brow*Ndim + bcol, Ndim, Kdim, smem);
}

__global__ __launch_bounds__(256) void sims3_kernel()
{
    extern __shared__ char smem[];
    int z = blockIdx.z, b = z >> 4, h = z & 15;
    int lbase = blockIdx.y * 128, mbase = blockIdx.x * 128;
    size_t aoff = ((size_t)b*LL + lbase)*DD + (size_t)h*DH;
    size_t boff = ((size_t)b*LL + mbase)*DH;
    mma_gemm_body3(g_qh + aoff, g_ql + aoff, DD,
                   g_kh + boff, g_kl + boff, DH,
                   g_sims + (size_t)z*LL*LL + (size_t)lbase*LL + mbase, LL, DH, smem);
}

// ---------------- pv: local = softmax(sims)@v via bf16x3 mma ----------------
__global__ __launch_bounds__(256) void pv_mma_kernel()
{
    extern __shared__ char smem[];
    float* smx = (float*)(smem + 49152);
    float* sis = (float*)(smem + 49664);
    int z = blockIdx.y, b = z >> 4, h = z & 15;
    int lbase = blockIdx.x * 128;
    const float* S = g_sims + (size_t)z*LL*LL;
    int tid = threadIdx.x, lane = tid & 31, wid = tid >> 5;
    if (tid < 128) {
        size_t row = (size_t)z*LL + lbase + tid;
        smx[tid] = g_rowmax[row];
        sis[tid] = 1.0f / g_rowsum[row];
    }
    __syncthreads();
    uint32_t sb = smem_u32(smem);
    int wm = wid >> 1, wn = wid & 1;
    int lrow = lane & 15, lhalf = lane >> 4;
    float acc[2][4][4];
#pragma unroll
    for (int i = 0; i < 2; i++)
#pragma unroll
        for (int j = 0; j < 4; j++)
#pragma unroll
            for (int q = 0; q < 4; q++) acc[i][j][q] = 0.f;

    int r0 = tid >> 3, cc = tid & 7;
    const __nv_bfloat16* Vh = g_vth + (size_t)b*DH*LL;
    const __nv_bfloat16* Vl = g_vtl + (size_t)b*DH*LL;

    for (int mt = 0; mt < LL; mt += 64) {
#pragma unroll
        for (int t = 0; t < 4; t++) {
            int r = r0 + t*32;
            const float* sp = S + (size_t)(lbase + r)*LL + mt + cc*8;
            float4 v0 = *(const float4*)sp;
            float4 v1 = *(const float4*)(sp + 4);
            float m = smx[r], is = sis[r];
            float e[8];
            e[0] = __expf((v0.x - m)*SCALE)*is; e[1] = __expf((v0.y - m)*SCALE)*is;
            e[2] = __expf((v0.z - m)*SCALE)*is; e[3] = __expf((v0.w - m)*SCALE)*is;
            e[4] = __expf((v1.x - m)*SCALE)*is; e[5] = __expf((v1.y - m)*SCALE)*is;
            e[6] = __expf((v1.z - m)*SCALE)*is; e[7] = __expf((v1.w - m)*SCALE)*is;
            float hf[8], lf[8];
#pragma unroll
            for (int j = 0; j < 8; j++) {
                hf[j] = __bfloat162float(__float2bfloat16(e[j]));
                lf[j] = e[j] - hf[j];
            }
            uint4 uh = make_uint4(bpack(hf[0],hf[1]), bpack(hf[2],hf[3]),
                                  bpack(hf[4],hf[5]), bpack(hf[6],hf[7]));
            uint4 ul = make_uint4(bpack(lf[0],lf[1]), bpack(lf[2],lf[3]),
                                  bpack(lf[4],lf[5]), bpack(lf[6],lf[7]));
            int off = r*128 + ((cc ^ (r & 7)) << 4);
            *(uint4*)(smem + off)         = uh;
            *(uint4*)(smem + 16384 + off) = ul;
        }
#pragma unroll
        for (int t = 0; t < 2; t++) {
            int idx = tid + t*256;
            int r = idx >> 3, c = idx & 7;
            int off = 32768 + r*128 + ((c ^ (r & 7)) << 4);
            *(uint4*)(smem + off)        = *(const uint4*)(Vh + (size_t)r*LL + mt + c*8);
            *(uint4*)(smem + off + 8192) = *(const uint4*)(Vl + (size_t)r*LL + mt + c*8);
        }
        __syncthreads();
#pragma unroll
        for (int s = 0; s < 4; s++) {
            int chunk = s*2 + lhalf;
            uint32_t ah[2][4], al[2][4], bh[4][2], bl[4][2];
#pragma unroll
            for (int mf = 0; mf < 2; mf++) {
                int row = wm*32 + mf*16 + lrow;
                uint32_t ad = sb + row*128 + ((chunk ^ (row & 7)) << 4);
                LDSM4(ah[mf][0], ah[mf][1], ah[mf][2], ah[mf][3], ad);
                LDSM4(al[mf][0], al[mf][1], al[mf][2], al[mf][3], ad + 16384);
            }
#pragma unroll
            for (int p = 0; p < 2; p++) {
                int row = wn*32 + p*16 + lrow;
                uint32_t bd = sb + 32768 + row*128 + ((chunk ^ (row & 7)) << 4);
                uint32_t t0, t1, t2, t3;
                LDSM4(t0, t1, t2, t3, bd);
                bh[p*2+0][0] = t0; bh[p*2+0][1] = t2;
                bh[p*2+1][0] = t1; bh[p*2+1][1] = t3;
                LDSM4(t0, t1, t2, t3, bd + 8192);
                bl[p*2+0][0] = t0; bl[p*2+0][1] = t2;
                bl[p*2+1][0] = t1; bl[p*2+1][1] = t3;
            }
#pragma unroll
            for (int mf = 0; mf < 2; mf++)
#pragma unroll
                for (int nf = 0; nf < 4; nf++) {
                    MMA_BF16(acc[mf][nf], ah[mf][0], ah[mf][1], ah[mf][2], ah[mf][3],
                             bh[nf][0], bh[nf][1]);
                    MMA_BF16(acc[mf][nf], ah[mf][0], ah[mf][1], ah[mf][2], ah[mf][3],
                             bl[nf][0], bl[nf][1]);
                    MMA_BF16(acc[mf][nf], al[mf][0], al[mf][1], al[mf][2], al[mf][3],
                             bh[nf][0], bh[nf][1]);
                }
        }
        __syncthreads();
    }
#pragma unroll
    for (int mf = 0; mf < 2; mf++) {
        int r = wm*32 + mf*16 + (lane >> 2);
#pragma unroll
        for (int nf = 0; nf < 4; nf++) {
            int c = wn*32 + nf*8 + (lane & 3)*2;
            float* p = g_attn + ((size_t)b*LL + lbase + r)*DD + h*DH + c;
            *(float2*)p                  = make_float2(acc[mf][nf][0], acc[mf][nf][1]);
            *(float2*)(p + (size_t)8*DD) = make_float2(acc[mf][nf][2], acc[mf][nf][3]);
        }
    }
}

// ---------------- split kernels ----------------
__global__ void split_kernel(const float* __restrict__ src,
                             __nv_bfloat16* __restrict__ hi, __nv_bfloat16* __restrict__ lo)
{
    int i = blockIdx.x*256 + threadIdx.x;
    float4 v = ((const float4*)src)[i];
    float vv[4] = {v.x, v.y, v.z, v.w};
#pragma unroll
    for (int j = 0; j < 4; j++) {
        __nv_bfloat16 h = __float2bfloat16(vv[j]);
        hi[i*4 + j] = h;
        lo[i*4 + j] = __float2bfloat16(vv[j] - __bfloat162float(h));
    }
}

__global__ void transpose_split_kernel(const float* __restrict__ src,
                                       __nv_bfloat16* __restrict__ hi,
                                       __nv_bfloat16* __restrict__ lo, int R, int Cn)
{
    __shared__ float t[32][33];
    int c0 = blockIdx.x*32, r0 = blockIdx.y*32;
    for (int i = threadIdx.y; i < 32; i += 8)
        t[i][threadIdx.x] = src[(size_t)(r0 + i)*Cn + c0 + threadIdx.x];
    __syncthreads();
    for (int i = threadIdx.y; i < 32; i += 8) {
        float x = t[threadIdx.x][i];
        __nv_bfloat16 h = __float2bfloat16(x);
        size_t o = (size_t)(c0 + i)*R + r0 + threadIdx.x;
        hi[o] = h;
        lo[o] = __float2bfloat16(x - __bfloat162float(h));
    }
}

// ---------------- sequence-axis L2 norm ----------------
__global__ void colsq_kernel() {
    int b = blockIdx.x >> 4, chunk = blockIdx.x & 15;
    int j = threadIdx.x & 127, p = threadIdx.x >> 7;
    const float* base = g_kv + ((size_t)b*LL + chunk*128)*128;
    float ss = 0.f;
    for (int ll = p; ll < 128; ll += 2) {
        float v = base[ll*128 + j];
        ss += v*v;
    }
    __shared__ float sh[256];
    sh[threadIdx.x] = ss;
    __syncthreads();
    if (p == 0) g_part[(size_t)blockIdx.x*128 + j] = ss + sh[128 + j];
}

__global__ void normsum_kernel() {
    int tid = threadIdx.x;
    int b = tid >> 7, j = tid & 127;
    float s = 0.f;
    for (int c = 0; c < 16; c++) s += g_part[(b*16 + c)*128 + j];
    g_norm[tid] = s;
}

__global__ void normalize_kernel() {
    int idx = blockIdx.x*256 + threadIdx.x;
    int j  = idx & 127;
    int bl = idx >> 7;
    int b  = bl >> 11;
    float n = sqrtf(g_norm[b*128 + j]);
    n = fmaxf(n, 1e-12f);
    float v = g_kv[(size_t)idx] / n;
    if (j < 64) {
        g_k[(size_t)bl*64 + j] = v;
        __nv_bfloat16 h = __float2bfloat16(v);
        g_kh[(size_t)bl*64 + j] = h;
        g_kl[(size_t)bl*64 + j] = __float2bfloat16(v - __bfloat162float(h));
    } else {
        g_v[(size_t)bl*64 + (j - 64)] = v;
    }
}

// ---------------- per-row: max, sumexp, coarse top-48 candidates ------------
__global__ __launch_bounds__(256) void stats_topk_kernel() {  // grid 65536
    __shared__ unsigned cand_key[320];
    __shared__ int      cand_idx[320];
    __shared__ float    redf[8];
    __shared__ unsigned redk[8];
    __shared__ float    s_mx;
    size_t row = blockIdx.x;
    const float* S = g_sims + row * LL;
    int tid = threadIdx.x, lane = tid & 31, wid = tid >> 5;

    float4 a = ((const float4*)S)[tid];
    float4 c = ((const float4*)S)[tid + 256];
    float v[8] = {a.x, a.y, a.z, a.w, c.x, c.y, c.z, c.w};
    unsigned key[8];
#pragma unroll
    for (int j = 0; j < 8; j++) key[j] = f2key(v[j]);

    unsigned km = key[0];
#pragma unroll
    for (int j = 1; j < 8; j++) km = max(km, key[j]);
    km = __reduce_max_sync(0xffffffffu, km);
    if (lane == 0) redk[wid] = km;
    __syncthreads();
    if (tid == 0) {
        unsigned m = redk[0];
        for (int w = 1; w < 8; w++) m = max(m, redk[w]);
        float mx = key2f(m);
        s_mx = mx;
        g_rowmax[row] = mx;
    }
    __syncthreads();
    float mx = s_mx;

    float ls = 0.f;
#pragma unroll
    for (int j = 0; j < 8; j++) ls += __expf((v[j] - mx)*SCALE);
#pragma unroll
    for (int o = 16; o; o >>= 1) ls += __shfl_xor_sync(0xffffffffu, ls, o);
    if (lane == 0) redf[wid] = ls;
    __syncthreads();
    if (tid == 0) {
        float t = 0.f;
        for (int w = 0; w < 8; w++) t += redf[w];
        g_rowsum[row] = t;
    }

    // per-warp top-40 of its 256 elements
    unsigned lk = 0; int lj = 0;
#pragma unroll
    for (int j = 0; j < 8; j++) if (key[j] > lk) { lk = key[j]; lj = j; }
    for (int it = 0; it < 40; it++) {
        unsigned w = __reduce_max_sync(0xffffffffu, lk);
        unsigned ball = __ballot_sync(0xffffffffu, lk == w);
        int src = __ffs(ball) - 1;
        if (lane == src) {
            cand_key[wid*40 + it] = w;
            cand_idx[wid*40 + it] = (lj < 4) ? (4*tid + lj) : (1024 + 4*tid + lj - 4);
            key[lj] = 0u;
            lk = 0; lj = 0;
#pragma unroll
            for (int j = 0; j < 8; j++) if (key[j] > lk) { lk = key[j]; lj = j; }
        }
    }
    __syncthreads();

    // warp 0 merges 320 candidates -> coarse top-48 indices
    if (wid == 0) {
        unsigned mkey[10]; int midx[10];
#pragma unroll
        for (int j = 0; j < 10; j++) {
            mkey[j] = cand_key[lane*10 + j];
            midx[j] = cand_idx[lane*10 + j];
        }
        unsigned mk = 0; int mj = 0;
#pragma unroll
        for (int j = 0; j < 10; j++) if (mkey[j] > mk) { mk = mkey[j]; mj = j; }
        for (int it = 0; it < NCAND; it++) {
            unsigned w = __reduce_max_sync(0xffffffffu, mk);
            unsigned ball = __ballot_sync(0xffffffffu, mk == w);
            int src = __ffs(ball) - 1;
            if (lane == src) {
                g_cand[row*NCAND + it] = midx[mj];
                mkey[mj] = 0u;
                mk = 0; mj = 0;
#pragma unroll
                for (int j = 0; j < 10; j++) if (mkey[j] > mk) { mk = mkey[j]; mj = j; }
            }
        }
    }
}

// ---------------- refine: sequential fp32 re-score + top-32 + retrieved -----
// STRICTLY sequential ascending-d fmaf chain: bitwise-matches the fp32 SIMT
// sims inner loop (and, per R2/R3 evidence, the reference's accumulation).
__device__ __forceinline__ float dot64_seq(const float* __restrict__ q,
                                           const float* __restrict__ k) {
    float s = 0.f;
#pragma unroll
    for (int i = 0; i < 64; i++) s = fmaf(q[i], k[i], s);
    return s;
}

__global__ __launch_bounds__(256) void refine_kernel() {  // grid 8192, warp/row
    __shared__ float qrow[8][64];
    __shared__ float sel_v[8][32];
    __shared__ int   sel_i[8][32];
    int wid = threadIdx.x >> 5, lane = threadIdx.x & 31;
    size_t row = (size_t)blockIdx.x*8 + wid;
    int z = (int)(row >> 11), l = (int)(row & 2047);
    int b = z >> 4, h = z & 15;

    const float* qp = g_q + ((size_t)b*LL + l)*DD + (size_t)h*DH;
    qrow[wid][lane]      = qp[lane];
    qrow[wid][lane + 32] = qp[lane + 32];
    __syncwarp();

    const float* kb = g_k + (size_t)b*LL*DH;
    int i0 = g_cand[row*NCAND + lane];
    float v0 = dot64_seq(qrow[wid], kb + (size_t)i0*DH);
    unsigned k0 = f2key(v0);
    int i1 = 0;
    unsigned k1 = 0u;
    if (lane < 16) {
        i1 = g_cand[row*NCAND + 32 + lane];
        float v1 = dot64_seq(qrow[wid], kb + (size_t)i1*DH);
        k1 = f2key(v1);
    }

    unsigned lk; int lj;
    if (k0 >= k1) { lk = k0; lj = 0; } else { lk = k1; lj = 1; }
    for (int it = 0; it < TK; it++) {
        unsigned w = __reduce_max_sync(0xffffffffu, lk);
        unsigned ball = __ballot_sync(0xffffffffu, lk == w);
        int src = __ffs(ball) - 1;
        if (lane == src) {
            sel_v[wid][it] = key2f(w);
            sel_i[wid][it] = (lj == 0) ? i0 : i1;
            if (lj == 0) k0 = 0u; else k1 = 0u;
            if (k0 >= k1) { lk = k0; lj = 0; } else { lk = k1; lj = 1; }
        }
    }
    __syncwarp();

    float tv = sel_v[wid][lane];
    float mx = sel_v[wid][0];
    float p = __expf((tv - mx)*SCALE);
    float psum = p;
#pragma unroll
    for (int o = 16; o; o >>= 1) psum += __shfl_xor_sync(0xffffffffu, psum, o);
    sel_v[wid][lane] = p / psum;
    __syncwarp();

    float a0 = 0.f, a1 = 0.f;
#pragma unroll 8
    for (int t = 0; t < TK; t++) {
        float w = sel_v[wid][t];
        const float* kr = kb + (size_t)sel_i[wid][t]*DH;
        a0 += w * kr[lane];
        a1 += w * kr[lane + 32];
    }
    size_t off = ((size_t)b*LL + l)*DD + (size_t)h*DH;
    g_attn[off + lane]      += a0;
    g_attn[off + lane + 32] += a1;
}

// ---------------- launch ----------------
extern "C" void kernel_launch(void* const* d_in, const int* in_sizes, int n_in,
                              void* d_out, int out_size)
{
    const float* q_in     = (const float*)d_in[0];
    const float* kv_in    = (const float*)d_in[1];
    const float* w_q      = (const float*)d_in[2];
    const float* w_kv     = (const float*)d_in[3];
    const float* w_concat = (const float*)d_in[4];
    float* out = (float*)d_out;

    float *p_q, *p_kv, *p_attn, *p_v;
    __nv_bfloat16 *p_ah, *p_al, *p_bth, *p_btl, *p_qh, *p_ql, *p_vth, *p_vtl;
    cudaGetSymbolAddress((void**)&p_q,    g_q);
    cudaGetSymbolAddress((void**)&p_kv,   g_kv);
    cudaGetSymbolAddress((void**)&p_attn, g_attn);
    cudaGetSymbolAddress((void**)&p_v,    g_v);
    cudaGetSymbolAddress((void**)&p_ah,   g_ah);
    cudaGetSymbolAddress((void**)&p_al,   g_al);
    cudaGetSymbolAddress((void**)&p_bth,  g_bth);
    cudaGetSymbolAddress((void**)&p_btl,  g_btl);
    cudaGetSymbolAddress((void**)&p_qh,   g_qh);
    cudaGetSymbolAddress((void**)&p_ql,   g_ql);
    cudaGetSymbolAddress((void**)&p_vth,  g_vth);
    cudaGetSymbolAddress((void**)&p_vtl,  g_vtl);

    static const int G3_SMEM = 65536;
    static const int PV_SMEM = 50176;
    cudaFuncSetAttribute(sims3_kernel,     cudaFuncAttributeMaxDynamicSharedMemorySize, G3_SMEM);
    cudaFuncSetAttribute(mma_gemm3_kernel, cudaFuncAttributeMaxDynamicSharedMemorySize, G3_SMEM);
    cudaFuncSetAttribute(pv_mma_kernel,    cudaFuncAttributeMaxDynamicSharedMemorySize, PV_SMEM);

    // 1. q = q_in @ w_q  (fp32 SIMT — sequential-k, selection-critical)
    sgemm_kernel<<<dim3(8, 32), 256>>>(q_in, w_q, p_q, BB*LL, DD, DD);
    // 2. kv = kv_in @ w_kv  (fp32 SIMT)
    sgemm_kernel<<<dim3(1, 32), 256>>>(kv_in, w_kv, p_kv, BB*LL, 2*DH, DD);
    // 3. l2 norm over sequence axis (+ k 2-split)
    colsq_kernel<<<32, 256>>>();
    normsum_kernel<<<1, 256>>>();
    normalize_kernel<<<2048, 256>>>();
    // 3b. v^T 2-split for pv
    transpose_split_kernel<<<dim3(2,64), dim3(32,8)>>>(p_v,          p_vth,         p_vtl,         LL, DH);
    transpose_split_kernel<<<dim3(2,64), dim3(32,8)>>>(p_v + LL*DH,  p_vth + DH*LL, p_vtl + DH*LL, LL, DH);
    // 4. sims = q @ k^T  (bf16x3 coarse — smooth use + candidate generation)
    split_kernel<<<4096, 256>>>(p_q, p_qh, p_ql);
    sims3_kernel<<<dim3(16,16,32), 256, G3_SMEM>>>();
    // 5. row stats + coarse top-48 candidates
    stats_topk_kernel<<<BB*HH*LL, 256>>>();
    // 6. local attention (P@V) -> g_attn  (bf16x3)
    pv_mma_kernel<<<dim3(16, 32), 256, PV_SMEM>>>();
    // 7. sequential-fp32 refine + retrieved (+= into g_attn)
    refine_kernel<<<BB*HH*LL/8, 256>>>();
    // 8. out = attn @ w_concat  (bf16x3 — proven harmless in R8/R9)
    transpose_split_kernel<<<dim3(32,32), dim3(32,8)>>>(w_concat, p_bth, p_btl, DD, DD);
    split_kernel<<<4096, 256>>>(p_attn, p_ah, p_al);
    mma_gemm3_kernel<<<dim3(8,32), 256, G3_SMEM>>>(p_ah, p_al, p_bth, p_btl, out, DD, DD);
}